// round 15
// baseline (speedup 1.0000x reference)
#include <cuda_runtime.h>
#include <cuda_fp16.h>
#include <math.h>

#define DIMN  1024
#define NH    16
#define HD    64
#define BATCH 2
#define SEQ   2048
#define MROWS (BATCH*SEQ)   // 4096

// ---------------- scratch (device globals; no allocations allowed) ----------
__device__ __half g_x16[MROWS*DIMN];
__device__ __half g_w16[4][DIMN*DIMN];     // Wq, Wk, Wv, Wo
__device__ float2 g_rope[SEQ*32];          // (cos, sin) per (s, d2)

// attention operands, [B,H,S,hd], fp16
__device__ __half g_q16 [MROWS*DIMN];      // pre-scaled by 0.125
__device__ __half g_k16 [MROWS*DIMN];
__device__ __half g_v16 [MROWS*DIMN];
__device__ __half g_att16[MROWS*DIMN];     // attention out, [B,S,D], fp16

// ---------------- helpers ----------------------------------------------------
__device__ __forceinline__ unsigned int smem_u32(const void* p) {
    return (unsigned int)__cvta_generic_to_shared(p);
}
__device__ __forceinline__ void cp16(unsigned int s, const void* g) {
    asm volatile("cp.async.cg.shared.global [%0], [%1], 16;\n" :: "r"(s), "l"(g));
}
__device__ __forceinline__ void cp_commit() {
    asm volatile("cp.async.commit_group;\n");
}
__device__ __forceinline__ void cp_wait2() {
    asm volatile("cp.async.wait_group 2;\n");
}
__device__ __forceinline__ void cp_wait0() {
    asm volatile("cp.async.wait_group 0;\n");
}
__device__ __forceinline__ void ldmx4(unsigned int addr, unsigned int& r0, unsigned int& r1,
                                      unsigned int& r2, unsigned int& r3) {
    asm volatile("ldmatrix.sync.aligned.m8n8.x4.shared.b16 {%0,%1,%2,%3}, [%4];\n"
                 : "=r"(r0), "=r"(r1), "=r"(r2), "=r"(r3) : "r"(addr));
}
__device__ __forceinline__ void ldmx4t(unsigned int addr, unsigned int& r0, unsigned int& r1,
                                       unsigned int& r2, unsigned int& r3) {
    asm volatile("ldmatrix.sync.aligned.m8n8.x4.trans.shared.b16 {%0,%1,%2,%3}, [%4];\n"
                 : "=r"(r0), "=r"(r1), "=r"(r2), "=r"(r3) : "r"(addr));
}
__device__ __forceinline__ void mma16816h(float* c, const unsigned int* a,
                                          unsigned int b0, unsigned int b1) {
    asm volatile("mma.sync.aligned.m16n8k16.row.col.f32.f16.f16.f32 "
                 "{%0,%1,%2,%3}, {%4,%5,%6,%7}, {%8,%9}, {%0,%1,%2,%3};\n"
                 : "+f"(c[0]), "+f"(c[1]), "+f"(c[2]), "+f"(c[3])
                 : "r"(a[0]), "r"(a[1]), "r"(a[2]), "r"(a[3]), "r"(b0), "r"(b1));
}
__device__ __forceinline__ unsigned short hfbits(float f) {
    __half h = __float2half_rn(f);
    return *reinterpret_cast<unsigned short*>(&h);
}
__device__ __forceinline__ unsigned int pk2h(float a, float b) {
    return (unsigned int)hfbits(a) | ((unsigned int)hfbits(b) << 16);
}

// ---------------- one-pass conversion + rope table (2 float4 / thread) -------
__global__ __launch_bounds__(256)
void conv_all(const float* __restrict__ x,  const float* __restrict__ wq,
              const float* __restrict__ wk, const float* __restrict__ wv,
              const float* __restrict__ wo)
{
    const int NX4 = MROWS*DIMN/4;
    const int NW4 = DIMN*DIMN/4;
    const int NCV = NX4 + 4*NW4;
    const int TOTAL = NCV + SEQ*32;
    const int stride = gridDim.x * blockDim.x;
    for (int i = blockIdx.x * blockDim.x + threadIdx.x; i < TOTAL; i += stride) {
        if (i < NCV) {
            const float* src; ushort4* dst; int off;
            if (i < NX4) {
                src = x; off = i;
                dst = reinterpret_cast<ushort4*>(g_x16);
            } else {
                int j = i - NX4;
                int w = j >> 18;
                off = j & (NW4 - 1);
                src = (w == 0) ? wq : (w == 1) ? wk : (w == 2) ? wv : wo;
                dst = reinterpret_cast<ushort4*>(&g_w16[w][0]);
            }
            float4 v = reinterpret_cast<const float4*>(src)[off];
            dst[off] = make_ushort4(hfbits(v.x), hfbits(v.y), hfbits(v.z), hfbits(v.w));
        } else {
            int idx = i - NCV;
            int d2 = idx & 31, s = idx >> 5;
            float inv = exp2f(-(float)d2 * 0.41524101186091403f);
            float ang = (float)s * inv;
            g_rope[idx] = make_float2(cosf(ang), sinf(ang));
        }
    }
}

// ---------------- fp16 GEMM: C = A @ W^T (R12 config) -------------------------
// CTA 128x128, 256 threads / 8 warps (2x4), warp tile 64x32.
// BK=32, 4-stage cp.async, one syncthreads per K-iteration.
// smem: A 4 stages x 8KB at +0; B 4 stages x 8KB at +32768. (64KB)
// mode 0: fp32 C; 1: V scatter -> g_v16; 2: Q rope (x0.125); 3: K rope
#define SSTR 132
#define GKT  32

__device__ __forceinline__ void gemm_f16_body(const __half* __restrict__ A,
                                              const __half* __restrict__ W,
                                              float* __restrict__ C, int mode)
{
    extern __shared__ __align__(16) char gsm[];
    __half* sA = reinterpret_cast<__half*>(gsm);
    __half* sB = reinterpret_cast<__half*>(gsm + 32768);
    float*  stage = reinterpret_cast<float*>(gsm);   // reused post-pipeline (modes 2/3)

    const int tid   = threadIdx.x;
    const int lane  = tid & 31;
    const int warp  = tid >> 5;
    const int wm    = warp >> 2;
    const int wn    = warp & 3;
    const int row0  = blockIdx.y * 128;
    const int col0  = blockIdx.x * 128;

    const int lrow = tid >> 1;
    const int lch  = tid & 1;
    const int lpc  = lch ^ ((lrow >> 2) & 1);
    const __half* Ap = A + (size_t)(row0 + lrow) * DIMN + lch * 8;
    const __half* Wp = W + (size_t)(col0 + lrow) * DIMN + lch * 8;
    const unsigned int aLd = smem_u32(sA + lrow * 16 + lpc * 8);
    const unsigned int bLd = smem_u32(sB + lrow * 16 + lpc * 8);

    float acc[4][4][4];
#pragma unroll
    for (int i = 0; i < 4; i++)
#pragma unroll
        for (int j = 0; j < 4; j++)
#pragma unroll
            for (int k = 0; k < 4; k++) acc[i][j][k] = 0.0f;

    unsigned int aAddr[4], bAddr[2];
#pragma unroll
    for (int mt = 0; mt < 4; mt++) {
        int r  = wm * 64 + mt * 16 + (lane & 15);
        int ch = lane >> 4;
        int pc = ch ^ ((r >> 2) & 1);
        aAddr[mt] = smem_u32(sA + r * 16 + pc * 8);
    }
#pragma unroll
    for (int p = 0; p < 2; p++) {
        int grp = lane >> 3;
        int r   = wn * 32 + p * 16 + (grp >> 1) * 8 + (lane & 7);
        int ch  = grp & 1;
        int pc  = ch ^ ((r >> 2) & 1);
        bAddr[p] = smem_u32(sB + r * 16 + pc * 8);
    }

    auto load_stage = [&](int kb, int s) {
        const __half* a = Ap + kb * 32;
        const __half* w = Wp + kb * 32;
#pragma unroll
        for (int sub = 0; sub < 2; sub++) {
            unsigned int so = s * 8192 + sub * 4096;
            cp16(aLd + so, a + sub * 16);
            cp16(bLd + so, w + sub * 16);
        }
    };

    load_stage(0, 0); cp_commit();
    load_stage(1, 1); cp_commit();

    for (int kt = 0; kt < GKT; kt++) {
        if (kt + 2 < GKT) load_stage(kt + 2, (kt + 2) & 3);
        cp_commit();
        cp_wait2();
        __syncthreads();

#pragma unroll
        for (int sub = 0; sub < 2; sub++) {
            unsigned int coff = (unsigned)((kt & 3) * 8192 + sub * 4096);
            unsigned int ah[4][4], bf[2][4];
#pragma unroll
            for (int mt = 0; mt < 4; mt++)
                ldmx4(aAddr[mt] + coff, ah[mt][0], ah[mt][1], ah[mt][2], ah[mt][3]);
#pragma unroll
            for (int p = 0; p < 2; p++)
                ldmx4(bAddr[p] + coff, bf[p][0], bf[p][1], bf[p][2], bf[p][3]);
#pragma unroll
            for (int mt = 0; mt < 4; mt++) {
#pragma unroll
                for (int nt = 0; nt < 4; nt++) {
                    int p = nt >> 1, s = nt & 1;
                    mma16816h(acc[mt][nt], ah[mt], bf[p][2*s], bf[p][2*s+1]);
                }
            }
        }
    }

    if (mode == 0) {
#pragma unroll
        for (int mt = 0; mt < 4; mt++) {
            int r = row0 + wm * 64 + mt * 16 + (lane >> 2);
#pragma unroll
            for (int nt = 0; nt < 4; nt++) {
                int c = col0 + wn * 32 + nt * 8 + (lane & 3) * 2;
                *reinterpret_cast<float2*>(&C[(size_t)r * DIMN + c]) =
                    make_float2(acc[mt][nt][0], acc[mt][nt][1]);
                *reinterpret_cast<float2*>(&C[(size_t)(r + 8) * DIMN + c]) =
                    make_float2(acc[mt][nt][2], acc[mt][nt][3]);
            }
        }
    } else if (mode == 1) {
#pragma unroll
        for (int mt = 0; mt < 4; mt++) {
            int r = row0 + wm * 64 + mt * 16 + (lane >> 2);
#pragma unroll
            for (int nt = 0; nt < 4; nt++) {
                int c = col0 + wn * 32 + nt * 8 + (lane & 3) * 2;
#pragma unroll
                for (int e = 0; e < 4; e++) {
                    int rr = r + (e >> 1) * 8;
                    int cc = c + (e & 1);
                    int b = rr >> 11, s = rr & (SEQ-1);
                    int h = cc >> 6,  d = cc & (HD-1);
                    size_t di = (((size_t)(b*NH + h))*SEQ + s)*HD + d;
                    reinterpret_cast<unsigned short*>(g_v16)[di] = hfbits(acc[mt][nt][e]);
                }
            }
        }
    } else {
        __syncthreads();   // all MMA smem reads complete before fp32 stage reuse
#pragma unroll
        for (int mt = 0; mt < 4; mt++) {
            int r = wm * 64 + mt * 16 + (lane >> 2);
#pragma unroll
            for (int nt = 0; nt < 4; nt++) {
                int c = wn * 32 + nt * 8 + (lane & 3) * 2;
                stage[r*SSTR + c]       = acc[mt][nt][0];
                stage[r*SSTR + c + 1]   = acc[mt][nt][1];
                stage[(r+8)*SSTR + c]   = acc[mt][nt][2];
                stage[(r+8)*SSTR + c+1] = acc[mt][nt][3];
            }
        }
        __syncthreads();

        const float qs = (mode == 2) ? 0.125f : 1.0f;
        __half* dstg = (mode == 2) ? g_q16 : g_k16;
        unsigned short* dp = reinterpret_cast<unsigned short*>(dstg);
#pragma unroll 4
        for (int i = 0; i < 64; i++) {
            int idx = i * 256 + tid;
            int r = idx >> 7, c = idx & 127;
            int sg = row0 + r;
            int b = sg >> 11, s = sg & (SEQ-1);
            int cg = col0 + c;
            int h = cg >> 6, d = cg & (HD-1);
            float2 cs = g_rope[s*32 + (d & 31)];
            float a = stage[r*SSTR + c];
            float p = stage[r*SSTR + (c ^ 32)];
            float out = (d < 32) ? (a*cs.x - p*cs.y) : (a*cs.x + p*cs.y);
            out *= qs;
            size_t di = (((size_t)(b*NH + h))*SEQ + s)*HD + d;
            dp[di] = hfbits(out);
        }
    }
}

__global__ __launch_bounds__(256)
void qkv_gemm_f16(const __half* __restrict__ x16)
{
    int z = blockIdx.z;
    if (z == 0)      gemm_f16_body(x16, g_w16[0], nullptr, 2);   // Q + rope
    else if (z == 1) gemm_f16_body(x16, g_w16[1], nullptr, 3);   // K + rope
    else             gemm_f16_body(x16, g_w16[2], nullptr, 1);   // V
}

__global__ __launch_bounds__(256)
void out_gemm_f16(float* __restrict__ C)
{
    gemm_f16_body(g_att16, g_w16[3], C, 0);
}

// ---------------- Flash attention (causal): BQ=128, 4-stage, 1 sync/tile ----
// Diagonal tiles: group-level skip of fully-masked S groups and all-zero P
// groups (bit-identical; masked entries are set to -INF by the mask loop,
// skipped PV groups contribute exact zeros).
#define FROWP 72

__device__ __forceinline__ int STI(int st, int r) {
    return (st*64 + r) * FROWP;
}

__global__ __launch_bounds__(256)
void flash_attn_mma()
{
    const int iq = (int)gridDim.x - 1 - (int)blockIdx.x;   // heavy tiles first
    const int h = blockIdx.y, b = blockIdx.z;
    const int q0 = iq * 128;
    const int tid = threadIdx.x, lane = tid & 31, warp = tid >> 5;
    const float LOG2E = 1.4426950408889634f;

    extern __shared__ __align__(16) __half fsm[];
    __half* sK = fsm;                       // 4 stages x 64 x 72
    __half* sV = fsm + 4*64*FROWP;

    const size_t bh = (size_t)(b*NH + h) * SEQ * HD;
    const __half* Qv = g_q16 + bh + (size_t)q0*HD;
    const __half* Kv = g_k16 + bh;
    const __half* Vv = g_v16 + bh;

    // ---- stage full Q (128 rows) across sK stage0+1 region ----
#pragma unroll
    for (int i = 0; i < 4; i++) {
        int id = tid + i * 256;
        int row = id >> 3, ch = id & 7;
        cp16(smem_u32(&sK[row*FROWP + ch*8]), Qv + row*HD + ch*8);
    }
    cp_commit(); cp_wait0();
    __syncthreads();

    unsigned int qf[4][4];
    {
        int r  = warp*16 + (lane & 15);
        int ch = (lane >> 4) * 8;
#pragma unroll
        for (int ks = 0; ks < 4; ks++)
            ldmx4(smem_u32(&sK[r*FROWP + ch + ks*16]),
                  qf[ks][0], qf[ks][1], qf[ks][2], qf[ks][3]);
    }
    __syncthreads();

    float oacc[8][4];
#pragma unroll
    for (int i = 0; i < 8; i++)
#pragma unroll
        for (int j = 0; j < 4; j++) oacc[i][j] = 0.0f;
    float m0 = -INFINITY, m1 = -INFINITY, l0 = 0.0f, l1 = 0.0f;

    const int nkv = 2 * (iq + 1);
    const int wbase = q0 + warp * 16;

    auto load_tile = [&](int t, int s) {
        const size_t go = (size_t)t * 64 * HD;
#pragma unroll
        for (int i = 0; i < 2; i++) {
            int id = tid + i * 256;
            int row = id >> 3, ch = id & 7;
            cp16(smem_u32(&sK[STI(s,row) + ch*8]), Kv + go + row*HD + ch*8);
            cp16(smem_u32(&sV[STI(s,row) + ch*8]), Vv + go + row*HD + ch*8);
        }
    };

    load_tile(0, 0); cp_commit();
    load_tile(1, 1); cp_commit();   // nkv >= 2 always

    for (int t = 0; t < nkv; t++) {
        if (t + 2 < nkv) load_tile(t + 2, (t + 2) & 3);
        cp_commit();
        cp_wait2();
        __syncthreads();
        const int st = t & 3;

        if (t * 64 <= wbase + 15) {
            const bool diag = (t * 64 + 63 > wbase);
            const int gmax = diag ? (((wbase + 15 - t * 64) >> 4) + 1) : 4;  // 1..4, warp-uniform

            float sacc[8][4];
#pragma unroll
            for (int i = 0; i < 8; i++)
#pragma unroll
                for (int j = 0; j < 4; j++) sacc[i][j] = 0.0f;

            {
                const int grp = lane >> 3;
                const int rb  = (grp >> 1) * 8 + (lane & 7);
                const int cb  = (grp & 1) * 8;
#pragma unroll
                for (int ks = 0; ks < 4; ks++) {
#pragma unroll
                    for (int p = 0; p < 4; p++) {
                        if (p < gmax) {
                            unsigned int kf[4];
                            ldmx4(smem_u32(&sK[STI(st,p*16+rb) + cb + ks*16]),
                                  kf[0], kf[1], kf[2], kf[3]);
#pragma unroll
                            for (int s = 0; s < 2; s++)
                                mma16816h(sacc[2*p+s], qf[ks], kf[2*s], kf[2*s+1]);
                        }
                    }
                }
            }

            const int quad = lane >> 2;
            const int cpair = (lane & 3) * 2;
            if (diag) {
                const int r0 = wbase + quad;
                const int kvb = t*64 + cpair;
#pragma unroll
                for (int nt = 0; nt < 8; nt++) {
#pragma unroll
                    for (int j = 0; j < 2; j++) {
                        int kg = kvb + nt*8 + j;
                        if (kg > r0)     sacc[nt][j]   = -INFINITY;
                        if (kg > r0 + 8) sacc[nt][2+j] = -INFINITY;
                    }
                }
            }

            float mx0 = -INFINITY, mx1 = -INFINITY;
#pragma unroll
            for (int nt = 0; nt < 8; nt++) {
                mx0 = fmaxf(mx0, fmaxf(sacc[nt][0], sacc[nt][1]));
                mx1 = fmaxf(mx1, fmaxf(sacc[nt][2], sacc[nt][3]));
            }
            mx0 = fmaxf(mx0, __shfl_xor_sync(0xffffffffu, mx0, 1));
            mx0 = fmaxf(mx0, __shfl_xor_sync(0xffffffffu, mx0, 2));
            mx1 = fmaxf(mx1, __shfl_xor_sync(0xffffffffu, mx1, 1));
            mx1 = fmaxf(mx1, __shfl_xor_sync(0xffffffffu, mx1, 2));

            float mn0 = fmaxf(m0, mx0), mn1 = fmaxf(m1, mx1);
            float a0 = exp2f((m0 - mn0) * LOG2E);
            float a1 = exp2f((m1 - mn1) * LOG2E);
            m0 = mn0; m1 = mn1;

            float s0 = 0.0f, s1 = 0.0f;
#pragma unroll
            for (int nt = 0; nt < 8; nt++) {
                float p0 = exp2f((sacc[nt][0] - mn0) * LOG2E);
                float p1 = exp2f((sacc[nt][1] - mn0) * LOG2E);
                float p2 = exp2f((sacc[nt][2] - mn1) * LOG2E);
                float p3 = exp2f((sacc[nt][3] - mn1) * LOG2E);
                sacc[nt][0] = p0; sacc[nt][1] = p1; sacc[nt][2] = p2; sacc[nt][3] = p3;
                s0 += p0 + p1; s1 += p2 + p3;
            }
            l0 = l0 * a0 + s0;
            l1 = l1 * a1 + s1;

#pragma unroll
            for (int nt = 0; nt < 8; nt++) {
                oacc[nt][0] *= a0; oacc[nt][1] *= a0;
                oacc[nt][2] *= a1; oacc[nt][3] *= a1;
            }

            unsigned int pf[4][4];
#pragma unroll
            for (int ks = 0; ks < 4; ks++) {
                if (ks < gmax) {
#pragma unroll
                    for (int half = 0; half < 2; half++) {
                        pf[ks][half]   = pk2h(sacc[2*ks][2*half],   sacc[2*ks][2*half+1]);
                        pf[ks][2+half] = pk2h(sacc[2*ks+1][2*half], sacc[2*ks+1][2*half+1]);
                    }
                }
            }

            {
                const int g   = lane >> 3;
                const int kvr = (g & 1) * 8 + (lane & 7);
                const int dcb = (g >> 1) * 8;
#pragma unroll
                for (int dt = 0; dt < 4; dt++) {
#pragma unroll
                    for (int ks = 0; ks < 4; ks++) {
                        if (ks < gmax) {
                            unsigned int vf[4];
                            ldmx4t(smem_u32(&sV[STI(st,ks*16+kvr) + dt*16 + dcb]),
                                   vf[0], vf[1], vf[2], vf[3]);
#pragma unroll
                            for (int s = 0; s < 2; s++)
                                mma16816h(oacc[2*dt+s], pf[ks], vf[2*s], vf[2*s+1]);
                        }
                    }
                }
            }
        }
    }

    // epilogue: quad-reduce l, then O/l -> g_att16 at [B,S,D]
    {
        l0 += __shfl_xor_sync(0xffffffffu, l0, 1);
        l0 += __shfl_xor_sync(0xffffffffu, l0, 2);
        l1 += __shfl_xor_sync(0xffffffffu, l1, 1);
        l1 += __shfl_xor_sync(0xffffffffu, l1, 2);

        const int quad = lane >> 2;
        const int cpair = (lane & 3) * 2;
        float il0 = 1.0f / l0, il1 = 1.0f / l1;
        int r0 = wbase + quad;
        unsigned short* AO = reinterpret_cast<unsigned short*>(g_att16);
#pragma unroll
        for (int nt = 0; nt < 8; nt++) {
            int d = nt*8 + cpair;
            size_t i0 = ((size_t)(b*SEQ) + r0)     * DIMN + h*HD + d;
            size_t i1 = ((size_t)(b*SEQ) + r0 + 8) * DIMN + h*HD + d;
            *reinterpret_cast<unsigned int*>(&AO[i0]) =
                pk2h(oacc[nt][0]*il0, oacc[nt][1]*il0);
            *reinterpret_cast<unsigned int*>(&AO[i1]) =
                pk2h(oacc[nt][2]*il1, oacc[nt][3]*il1);
        }
    }
}

// ---------------- launch ----------------------------------------------------
extern "C" void kernel_launch(void* const* d_in, const int* in_sizes, int n_in,
                              void* d_out, int out_size)
{
    const float* x  = (const float*)d_in[0];
    const float* Wq = (const float*)d_in[1];
    const float* Wk = (const float*)d_in[2];
    const float* Wv = (const float*)d_in[3];
    const float* Wo = (const float*)d_in[4];
    float* out = (float*)d_out;

    __half* x16;
    cudaGetSymbolAddress((void**)&x16, g_x16);

    const int NTOT4 = (MROWS*DIMN + 4*DIMN*DIMN) / 4 + SEQ*32;
    conv_all<<<(NTOT4/2 + 255)/256, 256>>>(x, Wq, Wk, Wv, Wo);

    const int QKV_SMEM = 128 * SSTR * 4;   // 67584 >= 65536 pipeline
    cudaFuncSetAttribute(qkv_gemm_f16, cudaFuncAttributeMaxDynamicSharedMemorySize, QKV_SMEM);
    dim3 gqkv(DIMN/128, MROWS/128, 3);
    qkv_gemm_f16<<<gqkv, 256, QKV_SMEM>>>(x16);

    const int FSM_BYTES = (4*64*FROWP + 4*64*FROWP) * 2;   // 73728
    cudaFuncSetAttribute(flash_attn_mma, cudaFuncAttributeMaxDynamicSharedMemorySize, FSM_BYTES);
    dim3 gfl(SEQ/128, NH, BATCH);
    flash_attn_mma<<<gfl, 256, FSM_BYTES>>>();

    const int OUT_SMEM = 65536;
    cudaFuncSetAttribute(out_gemm_f16, cudaFuncAttributeMaxDynamicSharedMemorySize, OUT_SMEM);
    dim3 gout(DIMN/128, MROWS/128);
    out_gemm_f16<<<gout, 256, OUT_SMEM>>>(out);
}

// round 16
// speedup vs baseline: 1.0613x; 1.0613x over previous
#include <cuda_runtime.h>
#include <cuda_fp16.h>
#include <math.h>

#define DIMN  1024
#define NH    16
#define HD    64
#define BATCH 2
#define SEQ   2048
#define MROWS (BATCH*SEQ)   // 4096

// ---------------- scratch (device globals; no allocations allowed) ----------
__device__ __half g_x16[MROWS*DIMN];
__device__ __half g_w16[4][DIMN*DIMN];     // Wq, Wk, Wv, Wo
__device__ float2 g_rope[SEQ*32];          // (cos, sin) per (s, d2)

// attention operands, [B,H,S,hd], fp16
__device__ __half g_q16 [MROWS*DIMN];      // pre-scaled by 0.125
__device__ __half g_k16 [MROWS*DIMN];
__device__ __half g_v16 [MROWS*DIMN];
__device__ __half g_att16[MROWS*DIMN];     // attention out, [B,S,D], fp16

// ---------------- helpers ----------------------------------------------------
__device__ __forceinline__ unsigned int smem_u32(const void* p) {
    return (unsigned int)__cvta_generic_to_shared(p);
}
__device__ __forceinline__ void cp16(unsigned int s, const void* g) {
    asm volatile("cp.async.cg.shared.global [%0], [%1], 16;\n" :: "r"(s), "l"(g));
}
__device__ __forceinline__ void cp_commit() {
    asm volatile("cp.async.commit_group;\n");
}
__device__ __forceinline__ void cp_wait2() {
    asm volatile("cp.async.wait_group 2;\n");
}
__device__ __forceinline__ void cp_wait0() {
    asm volatile("cp.async.wait_group 0;\n");
}
__device__ __forceinline__ void ldmx4(unsigned int addr, unsigned int& r0, unsigned int& r1,
                                      unsigned int& r2, unsigned int& r3) {
    asm volatile("ldmatrix.sync.aligned.m8n8.x4.shared.b16 {%0,%1,%2,%3}, [%4];\n"
                 : "=r"(r0), "=r"(r1), "=r"(r2), "=r"(r3) : "r"(addr));
}
__device__ __forceinline__ void ldmx4t(unsigned int addr, unsigned int& r0, unsigned int& r1,
                                       unsigned int& r2, unsigned int& r3) {
    asm volatile("ldmatrix.sync.aligned.m8n8.x4.trans.shared.b16 {%0,%1,%2,%3}, [%4];\n"
                 : "=r"(r0), "=r"(r1), "=r"(r2), "=r"(r3) : "r"(addr));
}
__device__ __forceinline__ void mma16816h(float* c, const unsigned int* a,
                                          unsigned int b0, unsigned int b1) {
    asm volatile("mma.sync.aligned.m16n8k16.row.col.f32.f16.f16.f32 "
                 "{%0,%1,%2,%3}, {%4,%5,%6,%7}, {%8,%9}, {%0,%1,%2,%3};\n"
                 : "+f"(c[0]), "+f"(c[1]), "+f"(c[2]), "+f"(c[3])
                 : "r"(a[0]), "r"(a[1]), "r"(a[2]), "r"(a[3]), "r"(b0), "r"(b1));
}
__device__ __forceinline__ unsigned short hfbits(float f) {
    __half h = __float2half_rn(f);
    return *reinterpret_cast<unsigned short*>(&h);
}
__device__ __forceinline__ unsigned int pk2h(float a, float b) {
    return (unsigned int)hfbits(a) | ((unsigned int)hfbits(b) << 16);
}

// ---------------- one-pass conversion + rope table (2 float4 / thread) -------
__global__ __launch_bounds__(256)
void conv_all(const float* __restrict__ x,  const float* __restrict__ wq,
              const float* __restrict__ wk, const float* __restrict__ wv,
              const float* __restrict__ wo)
{
    const int NX4 = MROWS*DIMN/4;
    const int NW4 = DIMN*DIMN/4;
    const int NCV = NX4 + 4*NW4;
    const int TOTAL = NCV + SEQ*32;
    const int stride = gridDim.x * blockDim.x;
    for (int i = blockIdx.x * blockDim.x + threadIdx.x; i < TOTAL; i += stride) {
        if (i < NCV) {
            const float* src; ushort4* dst; int off;
            if (i < NX4) {
                src = x; off = i;
                dst = reinterpret_cast<ushort4*>(g_x16);
            } else {
                int j = i - NX4;
                int w = j >> 18;
                off = j & (NW4 - 1);
                src = (w == 0) ? wq : (w == 1) ? wk : (w == 2) ? wv : wo;
                dst = reinterpret_cast<ushort4*>(&g_w16[w][0]);
            }
            float4 v = reinterpret_cast<const float4*>(src)[off];
            dst[off] = make_ushort4(hfbits(v.x), hfbits(v.y), hfbits(v.z), hfbits(v.w));
        } else {
            int idx = i - NCV;
            int d2 = idx & 31, s = idx >> 5;
            float inv = exp2f(-(float)d2 * 0.41524101186091403f);
            float ang = (float)s * inv;
            g_rope[idx] = make_float2(cosf(ang), sinf(ang));
        }
    }
}

// ---------------- fp16 GEMM: C = A @ W^T (R12 config) -------------------------
// CTA 128x128, 256 threads / 8 warps (2x4), warp tile 64x32.
// BK=32, 4-stage cp.async, one syncthreads per K-iteration.
// smem: A 4 stages x 8KB at +0; B 4 stages x 8KB at +32768. (64KB)
// mode 0: fp32 C; 1: V scatter -> g_v16; 2: Q rope (x0.125); 3: K rope
#define SSTR 132
#define GKT  32

__device__ __forceinline__ void gemm_f16_body(const __half* __restrict__ A,
                                              const __half* __restrict__ W,
                                              float* __restrict__ C, int mode)
{
    extern __shared__ __align__(16) char gsm[];
    __half* sA = reinterpret_cast<__half*>(gsm);
    __half* sB = reinterpret_cast<__half*>(gsm + 32768);
    float*  stage = reinterpret_cast<float*>(gsm);   // reused post-pipeline (modes 2/3)

    const int tid   = threadIdx.x;
    const int lane  = tid & 31;
    const int warp  = tid >> 5;
    const int wm    = warp >> 2;
    const int wn    = warp & 3;
    const int row0  = blockIdx.y * 128;
    const int col0  = blockIdx.x * 128;

    const int lrow = tid >> 1;
    const int lch  = tid & 1;
    const int lpc  = lch ^ ((lrow >> 2) & 1);
    const __half* Ap = A + (size_t)(row0 + lrow) * DIMN + lch * 8;
    const __half* Wp = W + (size_t)(col0 + lrow) * DIMN + lch * 8;
    const unsigned int aLd = smem_u32(sA + lrow * 16 + lpc * 8);
    const unsigned int bLd = smem_u32(sB + lrow * 16 + lpc * 8);

    float acc[4][4][4];
#pragma unroll
    for (int i = 0; i < 4; i++)
#pragma unroll
        for (int j = 0; j < 4; j++)
#pragma unroll
            for (int k = 0; k < 4; k++) acc[i][j][k] = 0.0f;

    unsigned int aAddr[4], bAddr[2];
#pragma unroll
    for (int mt = 0; mt < 4; mt++) {
        int r  = wm * 64 + mt * 16 + (lane & 15);
        int ch = lane >> 4;
        int pc = ch ^ ((r >> 2) & 1);
        aAddr[mt] = smem_u32(sA + r * 16 + pc * 8);
    }
#pragma unroll
    for (int p = 0; p < 2; p++) {
        int grp = lane >> 3;
        int r   = wn * 32 + p * 16 + (grp >> 1) * 8 + (lane & 7);
        int ch  = grp & 1;
        int pc  = ch ^ ((r >> 2) & 1);
        bAddr[p] = smem_u32(sB + r * 16 + pc * 8);
    }

    auto load_stage = [&](int kb, int s) {
        const __half* a = Ap + kb * 32;
        const __half* w = Wp + kb * 32;
#pragma unroll
        for (int sub = 0; sub < 2; sub++) {
            unsigned int so = s * 8192 + sub * 4096;
            cp16(aLd + so, a + sub * 16);
            cp16(bLd + so, w + sub * 16);
        }
    };

    load_stage(0, 0); cp_commit();
    load_stage(1, 1); cp_commit();

    for (int kt = 0; kt < GKT; kt++) {
        if (kt + 2 < GKT) load_stage(kt + 2, (kt + 2) & 3);
        cp_commit();
        cp_wait2();
        __syncthreads();

#pragma unroll
        for (int sub = 0; sub < 2; sub++) {
            unsigned int coff = (unsigned)((kt & 3) * 8192 + sub * 4096);
            unsigned int ah[4][4], bf[2][4];
#pragma unroll
            for (int mt = 0; mt < 4; mt++)
                ldmx4(aAddr[mt] + coff, ah[mt][0], ah[mt][1], ah[mt][2], ah[mt][3]);
#pragma unroll
            for (int p = 0; p < 2; p++)
                ldmx4(bAddr[p] + coff, bf[p][0], bf[p][1], bf[p][2], bf[p][3]);
#pragma unroll
            for (int mt = 0; mt < 4; mt++) {
#pragma unroll
                for (int nt = 0; nt < 4; nt++) {
                    int p = nt >> 1, s = nt & 1;
                    mma16816h(acc[mt][nt], ah[mt], bf[p][2*s], bf[p][2*s+1]);
                }
            }
        }
    }

    if (mode == 0) {
#pragma unroll
        for (int mt = 0; mt < 4; mt++) {
            int r = row0 + wm * 64 + mt * 16 + (lane >> 2);
#pragma unroll
            for (int nt = 0; nt < 4; nt++) {
                int c = col0 + wn * 32 + nt * 8 + (lane & 3) * 2;
                *reinterpret_cast<float2*>(&C[(size_t)r * DIMN + c]) =
                    make_float2(acc[mt][nt][0], acc[mt][nt][1]);
                *reinterpret_cast<float2*>(&C[(size_t)(r + 8) * DIMN + c]) =
                    make_float2(acc[mt][nt][2], acc[mt][nt][3]);
            }
        }
    } else if (mode == 1) {
#pragma unroll
        for (int mt = 0; mt < 4; mt++) {
            int r = row0 + wm * 64 + mt * 16 + (lane >> 2);
#pragma unroll
            for (int nt = 0; nt < 4; nt++) {
                int c = col0 + wn * 32 + nt * 8 + (lane & 3) * 2;
#pragma unroll
                for (int e = 0; e < 4; e++) {
                    int rr = r + (e >> 1) * 8;
                    int cc = c + (e & 1);
                    int b = rr >> 11, s = rr & (SEQ-1);
                    int h = cc >> 6,  d = cc & (HD-1);
                    size_t di = (((size_t)(b*NH + h))*SEQ + s)*HD + d;
                    reinterpret_cast<unsigned short*>(g_v16)[di] = hfbits(acc[mt][nt][e]);
                }
            }
        }
    } else {
        __syncthreads();   // all MMA smem reads complete before fp32 stage reuse
#pragma unroll
        for (int mt = 0; mt < 4; mt++) {
            int r = wm * 64 + mt * 16 + (lane >> 2);
#pragma unroll
            for (int nt = 0; nt < 4; nt++) {
                int c = wn * 32 + nt * 8 + (lane & 3) * 2;
                stage[r*SSTR + c]       = acc[mt][nt][0];
                stage[r*SSTR + c + 1]   = acc[mt][nt][1];
                stage[(r+8)*SSTR + c]   = acc[mt][nt][2];
                stage[(r+8)*SSTR + c+1] = acc[mt][nt][3];
            }
        }
        __syncthreads();

        const float qs = (mode == 2) ? 0.125f : 1.0f;
        __half* dstg = (mode == 2) ? g_q16 : g_k16;
        unsigned short* dp = reinterpret_cast<unsigned short*>(dstg);
#pragma unroll 4
        for (int i = 0; i < 64; i++) {
            int idx = i * 256 + tid;
            int r = idx >> 7, c = idx & 127;
            int sg = row0 + r;
            int b = sg >> 11, s = sg & (SEQ-1);
            int cg = col0 + c;
            int h = cg >> 6, d = cg & (HD-1);
            float2 cs = g_rope[s*32 + (d & 31)];
            float a = stage[r*SSTR + c];
            float p = stage[r*SSTR + (c ^ 32)];
            float out = (d < 32) ? (a*cs.x - p*cs.y) : (a*cs.x + p*cs.y);
            out *= qs;
            size_t di = (((size_t)(b*NH + h))*SEQ + s)*HD + d;
            dp[di] = hfbits(out);
        }
    }
}

__global__ __launch_bounds__(256)
void qkv_gemm_f16(const __half* __restrict__ x16)
{
    int z = blockIdx.z;
    if (z == 0)      gemm_f16_body(x16, g_w16[0], nullptr, 2);   // Q + rope
    else if (z == 1) gemm_f16_body(x16, g_w16[1], nullptr, 3);   // K + rope
    else             gemm_f16_body(x16, g_w16[2], nullptr, 1);   // V
}

__global__ __launch_bounds__(256)
void out_gemm_f16(float* __restrict__ C)
{
    gemm_f16_body(g_att16, g_w16[3], C, 0);
}

// ---------------- Flash attention (causal): BQ=128, 4-stage, 1 sync/tile ----
#define FROWP 72

__device__ __forceinline__ int STI(int st, int r) {
    return (st*64 + r) * FROWP;
}

__global__ __launch_bounds__(256)
void flash_attn_mma()
{
    const int iq = (int)gridDim.x - 1 - (int)blockIdx.x;   // heavy tiles first
    const int h = blockIdx.y, b = blockIdx.z;
    const int q0 = iq * 128;
    const int tid = threadIdx.x, lane = tid & 31, warp = tid >> 5;
    const float LOG2E = 1.4426950408889634f;

    extern __shared__ __align__(16) __half fsm[];
    __half* sK = fsm;                       // 4 stages x 64 x 72
    __half* sV = fsm + 4*64*FROWP;

    const size_t bh = (size_t)(b*NH + h) * SEQ * HD;
    const __half* Qv = g_q16 + bh + (size_t)q0*HD;
    const __half* Kv = g_k16 + bh;
    const __half* Vv = g_v16 + bh;

    // ---- stage full Q (128 rows) across sK stage0+1 region ----
#pragma unroll
    for (int i = 0; i < 4; i++) {
        int id = tid + i * 256;
        int row = id >> 3, ch = id & 7;
        cp16(smem_u32(&sK[row*FROWP + ch*8]), Qv + row*HD + ch*8);
    }
    cp_commit(); cp_wait0();
    __syncthreads();

    unsigned int qf[4][4];
    {
        int r  = warp*16 + (lane & 15);
        int ch = (lane >> 4) * 8;
#pragma unroll
        for (int ks = 0; ks < 4; ks++)
            ldmx4(smem_u32(&sK[r*FROWP + ch + ks*16]),
                  qf[ks][0], qf[ks][1], qf[ks][2], qf[ks][3]);
    }
    __syncthreads();

    float oacc[8][4];
#pragma unroll
    for (int i = 0; i < 8; i++)
#pragma unroll
        for (int j = 0; j < 4; j++) oacc[i][j] = 0.0f;
    float m0 = -INFINITY, m1 = -INFINITY, l0 = 0.0f, l1 = 0.0f;

    const int nkv = 2 * (iq + 1);
    const int wbase = q0 + warp * 16;

    auto load_tile = [&](int t, int s) {
        const size_t go = (size_t)t * 64 * HD;
#pragma unroll
        for (int i = 0; i < 2; i++) {
            int id = tid + i * 256;
            int row = id >> 3, ch = id & 7;
            cp16(smem_u32(&sK[STI(s,row) + ch*8]), Kv + go + row*HD + ch*8);
            cp16(smem_u32(&sV[STI(s,row) + ch*8]), Vv + go + row*HD + ch*8);
        }
    };

    load_tile(0, 0); cp_commit();
    load_tile(1, 1); cp_commit();   // nkv >= 2 always

    for (int t = 0; t < nkv; t++) {
        if (t + 2 < nkv) load_tile(t + 2, (t + 2) & 3);
        cp_commit();
        cp_wait2();
        __syncthreads();
        const int st = t & 3;

        if (t * 64 <= wbase + 15) {
            float sacc[8][4];
#pragma unroll
            for (int i = 0; i < 8; i++)
#pragma unroll
                for (int j = 0; j < 4; j++) sacc[i][j] = 0.0f;

            {
                const int grp = lane >> 3;
                const int rb  = (grp >> 1) * 8 + (lane & 7);
                const int cb  = (grp & 1) * 8;
#pragma unroll
                for (int ks = 0; ks < 4; ks++) {
#pragma unroll
                    for (int p = 0; p < 4; p++) {
                        unsigned int kf[4];
                        ldmx4(smem_u32(&sK[STI(st,p*16+rb) + cb + ks*16]),
                              kf[0], kf[1], kf[2], kf[3]);
#pragma unroll
                        for (int s = 0; s < 2; s++)
                            mma16816h(sacc[2*p+s], qf[ks], kf[2*s], kf[2*s+1]);
                    }
                }
            }

            const int quad = lane >> 2;
            const int cpair = (lane & 3) * 2;
            if (t * 64 + 63 > wbase) {
                const int r0 = wbase + quad;
                const int kvb = t*64 + cpair;
#pragma unroll
                for (int nt = 0; nt < 8; nt++) {
#pragma unroll
                    for (int j = 0; j < 2; j++) {
                        int kg = kvb + nt*8 + j;
                        if (kg > r0)     sacc[nt][j]   = -INFINITY;
                        if (kg > r0 + 8) sacc[nt][2+j] = -INFINITY;
                    }
                }
            }

            float mx0 = -INFINITY, mx1 = -INFINITY;
#pragma unroll
            for (int nt = 0; nt < 8; nt++) {
                mx0 = fmaxf(mx0, fmaxf(sacc[nt][0], sacc[nt][1]));
                mx1 = fmaxf(mx1, fmaxf(sacc[nt][2], sacc[nt][3]));
            }
            mx0 = fmaxf(mx0, __shfl_xor_sync(0xffffffffu, mx0, 1));
            mx0 = fmaxf(mx0, __shfl_xor_sync(0xffffffffu, mx0, 2));
            mx1 = fmaxf(mx1, __shfl_xor_sync(0xffffffffu, mx1, 1));
            mx1 = fmaxf(mx1, __shfl_xor_sync(0xffffffffu, mx1, 2));

            float mn0 = fmaxf(m0, mx0), mn1 = fmaxf(m1, mx1);
            float a0 = exp2f((m0 - mn0) * LOG2E);
            float a1 = exp2f((m1 - mn1) * LOG2E);
            m0 = mn0; m1 = mn1;

            float s0 = 0.0f, s1 = 0.0f;
#pragma unroll
            for (int nt = 0; nt < 8; nt++) {
                float p0 = exp2f((sacc[nt][0] - mn0) * LOG2E);
                float p1 = exp2f((sacc[nt][1] - mn0) * LOG2E);
                float p2 = exp2f((sacc[nt][2] - mn1) * LOG2E);
                float p3 = exp2f((sacc[nt][3] - mn1) * LOG2E);
                sacc[nt][0] = p0; sacc[nt][1] = p1; sacc[nt][2] = p2; sacc[nt][3] = p3;
                s0 += p0 + p1; s1 += p2 + p3;
            }
            l0 = l0 * a0 + s0;
            l1 = l1 * a1 + s1;

#pragma unroll
            for (int nt = 0; nt < 8; nt++) {
                oacc[nt][0] *= a0; oacc[nt][1] *= a0;
                oacc[nt][2] *= a1; oacc[nt][3] *= a1;
            }

            unsigned int pf[4][4];
#pragma unroll
            for (int ks = 0; ks < 4; ks++) {
#pragma unroll
                for (int half = 0; half < 2; half++) {
                    pf[ks][half]   = pk2h(sacc[2*ks][2*half],   sacc[2*ks][2*half+1]);
                    pf[ks][2+half] = pk2h(sacc[2*ks+1][2*half], sacc[2*ks+1][2*half+1]);
                }
            }

            {
                const int g   = lane >> 3;
                const int kvr = (g & 1) * 8 + (lane & 7);
                const int dcb = (g >> 1) * 8;
#pragma unroll
                for (int dt = 0; dt < 4; dt++) {
#pragma unroll
                    for (int ks = 0; ks < 4; ks++) {
                        unsigned int vf[4];
                        ldmx4t(smem_u32(&sV[STI(st,ks*16+kvr) + dt*16 + dcb]),
                               vf[0], vf[1], vf[2], vf[3]);
#pragma unroll
                        for (int s = 0; s < 2; s++)
                            mma16816h(oacc[2*dt+s], pf[ks], vf[2*s], vf[2*s+1]);
                    }
                }
            }
        }
    }

    // epilogue: quad-reduce l, then O/l -> g_att16 at [B,S,D]
    {
        l0 += __shfl_xor_sync(0xffffffffu, l0, 1);
        l0 += __shfl_xor_sync(0xffffffffu, l0, 2);
        l1 += __shfl_xor_sync(0xffffffffu, l1, 1);
        l1 += __shfl_xor_sync(0xffffffffu, l1, 2);

        const int quad = lane >> 2;
        const int cpair = (lane & 3) * 2;
        float il0 = 1.0f / l0, il1 = 1.0f / l1;
        int r0 = wbase + quad;
        unsigned short* AO = reinterpret_cast<unsigned short*>(g_att16);
#pragma unroll
        for (int nt = 0; nt < 8; nt++) {
            int d = nt*8 + cpair;
            size_t i0 = ((size_t)(b*SEQ) + r0)     * DIMN + h*HD + d;
            size_t i1 = ((size_t)(b*SEQ) + r0 + 8) * DIMN + h*HD + d;
            *reinterpret_cast<unsigned int*>(&AO[i0]) =
                pk2h(oacc[nt][0]*il0, oacc[nt][1]*il0);
            *reinterpret_cast<unsigned int*>(&AO[i1]) =
                pk2h(oacc[nt][2]*il1, oacc[nt][3]*il1);
        }
    }
}

// ---------------- launch ----------------------------------------------------
extern "C" void kernel_launch(void* const* d_in, const int* in_sizes, int n_in,
                              void* d_out, int out_size)
{
    const float* x  = (const float*)d_in[0];
    const float* Wq = (const float*)d_in[1];
    const float* Wk = (const float*)d_in[2];
    const float* Wv = (const float*)d_in[3];
    const float* Wo = (const float*)d_in[4];
    float* out = (float*)d_out;

    __half* x16;
    cudaGetSymbolAddress((void**)&x16, g_x16);

    const int NTOT4 = (MROWS*DIMN + 4*DIMN*DIMN) / 4 + SEQ*32;
    conv_all<<<(NTOT4/2 + 255)/256, 256>>>(x, Wq, Wk, Wv, Wo);

    const int QKV_SMEM = 128 * SSTR * 4;   // 67584 >= 65536 pipeline
    cudaFuncSetAttribute(qkv_gemm_f16, cudaFuncAttributeMaxDynamicSharedMemorySize, QKV_SMEM);
    dim3 gqkv(DIMN/128, MROWS/128, 3);
    qkv_gemm_f16<<<gqkv, 256, QKV_SMEM>>>(x16);

    const int FSM_BYTES = (4*64*FROWP + 4*64*FROWP) * 2;   // 73728
    cudaFuncSetAttribute(flash_attn_mma, cudaFuncAttributeMaxDynamicSharedMemorySize, FSM_BYTES);
    dim3 gfl(SEQ/128, NH, BATCH);
    flash_attn_mma<<<gfl, 256, FSM_BYTES>>>();

    const int OUT_SMEM = 65536;
    cudaFuncSetAttribute(out_gemm_f16, cudaFuncAttributeMaxDynamicSharedMemorySize, OUT_SMEM);
    dim3 gout(DIMN/128, MROWS/128);
    out_gemm_f16<<<gout, 256, OUT_SMEM>>>(out);
}